// round 15
// baseline (speedup 1.0000x reference)
#include <cuda_runtime.h>
#include <cuda_fp16.h>
#include <cstdint>

#define N_NODES 100000
#define N_EDGES 800000
#define H 128
#define HH (H*H)
#define NB ((N_NODES + 255) / 256)   // 391 scan blocks

// ---- scratch (no cudaMalloc allowed) ----
__device__ __half g_bufA[N_NODES * H];
__device__ __half g_bufB[N_NODES * H];
__device__ __half g_Plh[N_NODES * H];
__device__ __half g_Prh[N_NODES * H];
__device__ __half g_WsT[3 * H * 256];   // [l][n=128][k=256] : k<128 Wl^T, k>=128 Wr^T
__device__ __half g_W1T[256 * H];       // [n'=256][k=128]   : n'<128 Pl cols, else Pr
__device__ __half g_W2T[64 * H];        // [n=64][k=128] fp16 W2^T
// CSR scratch
__device__ int g_degi[N_NODES];
__device__ int g_loc[N_NODES];
__device__ int g_bsum[512];
__device__ int g_boff[512];
__device__ int g_off[N_NODES + 1];
__device__ int g_cur[N_NODES];
__device__ int g_csr[N_EDGES];

// ---- packed fp32x2 helpers ----
__device__ __forceinline__ unsigned long long pk2(float x, float y) {
    unsigned long long r;
    asm("mov.b64 %0, {%1, %2};" : "=l"(r) : "f"(x), "f"(y));
    return r;
}
__device__ __forceinline__ unsigned long long dup2(float x) { return pk2(x, x); }
__device__ __forceinline__ void fma2(unsigned long long& d, unsigned long long a,
                                     unsigned long long b) {
    asm("fma.rn.f32x2 %0, %1, %2, %0;" : "+l"(d) : "l"(a), "l"(b));
}
__device__ __forceinline__ float2 upk2(unsigned long long v) {
    float2 f;
    asm("mov.b64 {%0, %1}, %2;" : "=f"(f.x), "=f"(f.y) : "l"(v));
    return f;
}
// fp16 pack/unpack
__device__ __forceinline__ float2 h2f(unsigned int u) {
    __half2 h = *reinterpret_cast<__half2*>(&u);
    return __half22float2(h);
}
__device__ __forceinline__ unsigned int f2h2(float lo, float hi) {
    __half2 h = __floats2half2_rn(lo, hi);
    return *reinterpret_cast<unsigned int*>(&h);
}
__device__ __forceinline__ uint32_t smem_u32(const void* p) {
    uint32_t a;
    asm("{ .reg .u64 t; cvta.to.shared.u64 t, %1; cvt.u32.u64 %0, t; }" : "=r"(a) : "l"(p));
    return a;
}

// ---- mma helpers (verified R7..R13) ----
__device__ __forceinline__ void ldmA(uint32_t& a0, uint32_t& a1, uint32_t& a2, uint32_t& a3,
                                     uint32_t addr) {
    asm volatile("ldmatrix.sync.aligned.m8n8.x4.shared.b16 {%0,%1,%2,%3}, [%4];"
                 : "=r"(a0), "=r"(a1), "=r"(a2), "=r"(a3) : "r"(addr));
}
__device__ __forceinline__ void ldmB(uint32_t& b0, uint32_t& b1, uint32_t addr) {
    asm volatile("ldmatrix.sync.aligned.m8n8.x2.shared.b16 {%0,%1}, [%2];"
                 : "=r"(b0), "=r"(b1) : "r"(addr));
}
__device__ __forceinline__ void mma16816(float* c, uint32_t a0, uint32_t a1, uint32_t a2,
                                         uint32_t a3, uint32_t b0, uint32_t b1) {
    asm volatile(
        "mma.sync.aligned.m16n8k16.row.col.f32.f16.f16.f32 "
        "{%0,%1,%2,%3}, {%4,%5,%6,%7}, {%8,%9}, {%0,%1,%2,%3};"
        : "+f"(c[0]), "+f"(c[1]), "+f"(c[2]), "+f"(c[3])
        : "r"(a0), "r"(a1), "r"(a2), "r"(a3), "r"(b0), "r"(b1));
}

// ---------------- degree ----------------
__global__ void k_deg(const int* __restrict__ dst, int* __restrict__ degi) {
    int e = blockIdx.x * 256 + threadIdx.x;
    if (e < N_EDGES) atomicAdd(degi + dst[e], 1);
}

// ---------------- CSR build: block scan + fill ----------------
__global__ void k_scan1(const int* __restrict__ degi, int* __restrict__ loc,
                        int* __restrict__ bsum) {
    __shared__ int sm[256];
    int tid = threadIdx.x;
    int gid = blockIdx.x * 256 + tid;
    int v = (gid < N_NODES) ? degi[gid] : 0;
    sm[tid] = v;
    __syncthreads();
#pragma unroll
    for (int o = 1; o < 256; o <<= 1) {
        int y = (tid >= o) ? sm[tid - o] : 0;
        __syncthreads();
        sm[tid] += y;
        __syncthreads();
    }
    if (gid < N_NODES) loc[gid] = sm[tid] - v;
    if (tid == 255) bsum[blockIdx.x] = sm[255];
}
__global__ void k_scan2(const int* __restrict__ bsum, int* __restrict__ boff) {
    __shared__ int sm[512];
    int tid = threadIdx.x;
    int v = (tid < NB) ? bsum[tid] : 0;
    sm[tid] = v;
    __syncthreads();
#pragma unroll
    for (int o = 1; o < 512; o <<= 1) {
        int y = (tid >= o) ? sm[tid - o] : 0;
        __syncthreads();
        sm[tid] += y;
        __syncthreads();
    }
    if (tid < NB) boff[tid] = sm[tid] - v;
}
__global__ void k_scan3(const int* __restrict__ loc, const int* __restrict__ boff,
                        int* __restrict__ off, int* __restrict__ cur) {
    int gid = blockIdx.x * 256 + threadIdx.x;
    if (gid < N_NODES) {
        int o = loc[gid] + boff[gid >> 8];
        off[gid] = o;
        cur[gid] = o;
    }
    if (gid == 0) off[N_NODES] = N_EDGES;
}
__global__ void k_csrfill(const int* __restrict__ src, const int* __restrict__ dst,
                          int* __restrict__ cur, int* __restrict__ csr) {
    int e = blockIdx.x * 256 + threadIdx.x;
    if (e < N_EDGES) {
        int d = dst[e];
        int slot = atomicAdd(cur + d, 1);
        csr[slot] = src[e];
    }
}

// ---------------- weight prep: transposed fp16 copies (incl. W2^T) ----------------
__global__ void k_wprep(const float* __restrict__ sWl, const float* __restrict__ sWr,
                        const float* __restrict__ W1, const float* __restrict__ W2,
                        __half* __restrict__ WsT, __half* __restrict__ W1T,
                        __half* __restrict__ W2T) {
    int i = blockIdx.x * 256 + threadIdx.x;
    if (i < 3 * 128 * 256) {
        int l = i / (128 * 256);
        int rem = i - l * (128 * 256);
        int n = rem >> 8;
        int k = rem & 255;
        float v = (k < 128) ? sWl[l * HH + k * H + n] : sWr[l * HH + (k - 128) * H + n];
        WsT[i] = __float2half_rn(v);
    }
    if (i < 256 * 128) {
        int n = i >> 7, k = i & 127;
        float v = (n < 128) ? W1[k * H + n] : W1[(128 + k) * H + (n - 128)];
        W1T[i] = __float2half_rn(v);
    }
    if (i < 64 * 128) {
        int n = i >> 7, k = i & 127;
        W2T[i] = __float2half_rn(W2[k * 64 + n]);
    }
}

// ---------------- node projection -> fp16 h ----------------
__global__ void __launch_bounds__(256) k_nodeproj(
    const float* __restrict__ x, const float* __restrict__ W,
    const float* __restrict__ b, __half* __restrict__ h) {
    __shared__ float Ws[5 * 128];
    __shared__ float bs[128];
    int t = threadIdx.x;
    if (t < 128) bs[t] = b[t];
    for (int i = t; i < 640; i += 256) Ws[i] = W[i];
    __syncthreads();
    int id = blockIdx.x * 256 + t;
    int node = id >> 4;
    if (node >= N_NODES) return;
    int c0 = (id & 15) * 8;
    float xv[5];
#pragma unroll
    for (int k = 0; k < 5; k++) xv[k] = x[node * 5 + k];
    float a[8];
#pragma unroll
    for (int j = 0; j < 8; j++) a[j] = bs[c0 + j];
#pragma unroll
    for (int k = 0; k < 5; k++)
#pragma unroll
        for (int j = 0; j < 8; j++)
            a[j] = fmaf(xv[k], Ws[k * 128 + c0 + j], a[j]);
    uint4 o;
    o.x = f2h2(a[0], a[1]); o.y = f2h2(a[2], a[3]);
    o.z = f2h2(a[4], a[5]); o.w = f2h2(a[6], a[7]);
    *(uint4*)(h + (size_t)node * H + c0) = o;
}

// ---------------- CSR gather mean (inv fused from offsets) ----------------
__global__ void k_gather(const int* __restrict__ off, const int* __restrict__ csr,
                         const __half* __restrict__ h, __half* __restrict__ agg) {
    int node = (blockIdx.x * blockDim.x + threadIdx.x) >> 5;
    int lane = threadIdx.x & 31;
    if (node >= N_NODES) return;
    int b = off[node], e = off[node + 1];
    float a0 = 0.f, a1 = 0.f, a2 = 0.f, a3 = 0.f;
    for (int i = b; i < e; i++) {
        int s = csr[i];
        uint2 v = ((const uint2*)(h + (size_t)s * H))[lane];
        float2 f0 = h2f(v.x), f1 = h2f(v.y);
        a0 += f0.x; a1 += f0.y; a2 += f1.x; a3 += f1.y;
    }
    float iv = (e > b) ? 1.f / (float)(e - b) : 0.f;
    uint2 o;
    o.x = f2h2(a0 * iv, a1 * iv);
    o.y = f2h2(a2 * iv, a3 * iv);
    ((uint2*)(agg + (size_t)node * H))[lane] = o;
}

// ---------------- SAGE on HMMA fp16 (verified R11/R13) ----------------
#define SG_AS 0            // 128*144 = 18432 B
#define SG_WS 18432        // 128*144 = 18432 B
#define SG_LN 36864        // 384 f32 = 1536 B
#define SG_SM 38400
__global__ void __launch_bounds__(256) k_sage_mma(
    const __half* __restrict__ hX, __half* __restrict__ aggY,
    const __half* __restrict__ WsTl, const float* __restrict__ bl,
    const float* __restrict__ lg, const float* __restrict__ lb)
{
    extern __shared__ char smc[];
    uint32_t sb = smem_u32(smc);
    int t = threadIdx.x, lane = t & 31, warp = t >> 5;
    int row0 = blockIdx.x * 128;
    float* lns = (float*)(smc + SG_LN);
    if (t < 128) { lns[t] = bl[t]; lns[128 + t] = lg[t]; lns[256 + t] = lb[t]; }

    float acc[16][4];
#pragma unroll
    for (int nt = 0; nt < 16; nt++)
#pragma unroll
        for (int m = 0; m < 4; m++) acc[nt][m] = 0.f;

    for (int c = 0; c < 4; c++) {
        const __half* Usrc = (c < 2) ? aggY : hX;
        int kcol = (c & 1) * 64;
        __syncthreads();
#pragma unroll
        for (int p = 0; p < 8; p++) {
            int id = t + p * 256;
            int r = id >> 4, fq = id & 15;
            int row = row0 + r;
            uint2 v = make_uint2(0u, 0u);
            if (row < N_NODES)
                v = *(const uint2*)(Usrc + (size_t)row * H + kcol + fq * 4);
            *(uint2*)(smc + SG_AS + r * 144 + fq * 8) = v;
        }
#pragma unroll
        for (int p = 0; p < 4; p++) {
            int id = t + p * 256;
            int n = id >> 3, q = id & 7;
            uint4 w = *(const uint4*)(WsTl + n * 256 + c * 64 + q * 8);
            *(uint4*)(smc + SG_WS + n * 144 + q * 16) = w;
        }
        __syncthreads();
        uint32_t a_base = sb + SG_AS + (uint32_t)(warp * 16 + (lane & 15)) * 144
                          + (uint32_t)(lane >> 4) * 16;
        uint32_t b_base = sb + SG_WS + (uint32_t)(lane & 7) * 144
                          + (uint32_t)((lane >> 3) & 1) * 16;
#pragma unroll
        for (int ks = 0; ks < 4; ks++) {
            uint32_t a0, a1, a2, a3;
            ldmA(a0, a1, a2, a3, a_base + ks * 32);
#pragma unroll
            for (int nt = 0; nt < 16; nt++) {
                uint32_t b0, b1;
                ldmB(b0, b1, b_base + (uint32_t)nt * 8 * 144 + ks * 32);
                mma16816(acc[nt], a0, a1, a2, a3, b0, b1);
            }
        }
    }

    int qr = lane >> 2, qc = (lane & 3) * 2;
    int r0 = row0 + warp * 16 + qr;
    int r1 = r0 + 8;
    float s0 = 0.f, s1 = 0.f;
#pragma unroll
    for (int nt = 0; nt < 16; nt++) {
        int c0 = nt * 8 + qc;
        float bb0 = lns[c0], bb1 = lns[c0 + 1];
        acc[nt][0] += bb0; acc[nt][1] += bb1;
        acc[nt][2] += bb0; acc[nt][3] += bb1;
        s0 += acc[nt][0] + acc[nt][1];
        s1 += acc[nt][2] + acc[nt][3];
    }
    s0 += __shfl_xor_sync(0xffffffffu, s0, 1);
    s0 += __shfl_xor_sync(0xffffffffu, s0, 2);
    s1 += __shfl_xor_sync(0xffffffffu, s1, 1);
    s1 += __shfl_xor_sync(0xffffffffu, s1, 2);
    float mu0 = s0 * (1.f / 128.f), mu1 = s1 * (1.f / 128.f);
    float q0 = 0.f, q1 = 0.f;
#pragma unroll
    for (int nt = 0; nt < 16; nt++) {
        float d0 = acc[nt][0] - mu0, d1 = acc[nt][1] - mu0;
        float d2 = acc[nt][2] - mu1, d3 = acc[nt][3] - mu1;
        q0 = fmaf(d0, d0, q0); q0 = fmaf(d1, d1, q0);
        q1 = fmaf(d2, d2, q1); q1 = fmaf(d3, d3, q1);
    }
    q0 += __shfl_xor_sync(0xffffffffu, q0, 1);
    q0 += __shfl_xor_sync(0xffffffffu, q0, 2);
    q1 += __shfl_xor_sync(0xffffffffu, q1, 1);
    q1 += __shfl_xor_sync(0xffffffffu, q1, 2);
    float rs0 = rsqrtf(q0 * (1.f / 128.f) + 1e-5f);
    float rs1 = rsqrtf(q1 * (1.f / 128.f) + 1e-5f);
#pragma unroll
    for (int nt = 0; nt < 16; nt++) {
        int c0 = nt * 8 + qc;
        float g0 = lns[128 + c0], g1 = lns[128 + c0 + 1];
        float o0 = lns[256 + c0], o1 = lns[256 + c0 + 1];
        if (r0 < N_NODES) {
            *(unsigned*)(aggY + (size_t)r0 * H + c0) = f2h2(
                fmaxf(fmaf((acc[nt][0] - mu0) * rs0, g0, o0), 0.f),
                fmaxf(fmaf((acc[nt][1] - mu0) * rs0, g1, o1), 0.f));
        }
        if (r1 < N_NODES) {
            *(unsigned*)(aggY + (size_t)r1 * H + c0) = f2h2(
                fmaxf(fmaf((acc[nt][2] - mu1) * rs1, g0, o0), 0.f),
                fmaxf(fmaf((acc[nt][3] - mu1) * rs1, g1, o1), 0.f));
        }
    }
}

// ---------------- Pl/Pr on HMMA fp16 (verified R10-R13) ----------------
#define PP_AS 0            // 64*272 = 17408 B
#define PP_WS 17408        // 256*272 = 69632 B
#define PP_B1 87040        // 128 f32
#define PP_SM 87552
__global__ void __launch_bounds__(256) k_plpr_mma(
    const __half* __restrict__ h, const __half* __restrict__ W1T,
    const float* __restrict__ b1,
    __half* __restrict__ Pl, __half* __restrict__ Pr)
{
    extern __shared__ char smc[];
    uint32_t sb = smem_u32(smc);
    int t = threadIdx.x, lane = t & 31, warp = t >> 5;
    int row0 = blockIdx.x * 64;
    int half_ = warp >> 2;
    int wm = warp & 3;
    float* b1s = (float*)(smc + PP_B1);
    if (t < 128) b1s[t] = b1[t];

#pragma unroll
    for (int p = 0; p < 4; p++) {
        int id = t + p * 256;
        int r = id >> 4, fq = id & 15;
        int row = row0 + r;
        uint4 v = make_uint4(0u, 0u, 0u, 0u);
        if (row < N_NODES)
            v = *(const uint4*)(h + (size_t)row * H + fq * 8);
        *(uint4*)(smc + PP_AS + r * 272 + fq * 16) = v;
    }
#pragma unroll
    for (int p = 0; p < 16; p++) {
        int id = t + p * 256;
        int n = id >> 4, q = id & 15;
        uint4 w = *(const uint4*)(W1T + n * 128 + q * 8);
        *(uint4*)(smc + PP_WS + n * 272 + q * 16) = w;
    }
    __syncthreads();

    float acc[16][4];
#pragma unroll
    for (int nt = 0; nt < 16; nt++)
#pragma unroll
        for (int m = 0; m < 4; m++) acc[nt][m] = 0.f;

    uint32_t a_base = sb + PP_AS + (uint32_t)(wm * 16 + (lane & 15)) * 272
                      + (uint32_t)(lane >> 4) * 16;
    uint32_t b_base = sb + PP_WS + (uint32_t)half_ * 128 * 272
                      + (uint32_t)(lane & 7) * 272 + (uint32_t)((lane >> 3) & 1) * 16;
#pragma unroll
    for (int ks = 0; ks < 8; ks++) {
        uint32_t a0, a1, a2, a3;
        ldmA(a0, a1, a2, a3, a_base + ks * 32);
#pragma unroll
        for (int nt = 0; nt < 16; nt++) {
            uint32_t b0, b1v;
            ldmB(b0, b1v, b_base + (uint32_t)nt * 8 * 272 + ks * 32);
            mma16816(acc[nt], a0, a1, a2, a3, b0, b1v);
        }
    }

    int qr = lane >> 2, qc = (lane & 3) * 2;
    int r0 = row0 + wm * 16 + qr;
    int r1 = r0 + 8;
    __half* outp = half_ ? Pr : Pl;
#pragma unroll
    for (int nt = 0; nt < 16; nt++) {
        int c0 = nt * 8 + qc;
        float add0 = half_ ? 0.f : b1s[c0];
        float add1 = half_ ? 0.f : b1s[c0 + 1];
        if (r0 < N_NODES)
            *(unsigned*)(outp + (size_t)r0 * H + c0) = f2h2(acc[nt][0] + add0, acc[nt][1] + add1);
        if (r1 < N_NODES)
            *(unsigned*)(outp + (size_t)r1 * H + c0) = f2h2(acc[nt][2] + add0, acc[nt][3] + add1);
    }
}

// ---------------- fused edge MLP; TE=256, 512 threads (verified R13) ----------------
#define TE 256
#define ZST 136
#define EZ1_OFF   0                        // 256*272 = 69632
#define EW2T_OFF  69632                    // 64*272  = 17408
#define EW1_OFF   87040                    // 12*128 f32 = 6144
#define EW3_OFF   93184                    // 64 f32
#define EB2_OFF   93440                    // 64 f32
#define ESM_TOTAL 93696

__global__ void __launch_bounds__(512) k_edge(
    const int* __restrict__ src, const int* __restrict__ dst,
    const float* __restrict__ ea, const __half* __restrict__ Pl,
    const __half* __restrict__ Pr, const float* __restrict__ W1,
    const __half* __restrict__ W2T, const float* __restrict__ b2,
    const float* __restrict__ W3, const float* __restrict__ b3,
    float* __restrict__ out)
{
    extern __shared__ char smc[];
    uint32_t sb = smem_u32(smc);

    float* W1es = (float*)(smc + EW1_OFF);
    float* W3s  = (float*)(smc + EW3_OFF);
    float* b2s  = (float*)(smc + EB2_OFF);

    int t = threadIdx.x;

    for (int i = t; i < 12 * 128 / 4; i += 512)
        ((float4*)W1es)[i] = ((const float4*)(W1 + 256 * H))[i];
    if (t < 64) { W3s[t] = W3[t]; b2s[t] = b2[t]; }
#pragma unroll
    for (int p = 0; p < 2; p++) {
        int id = t + p * 512;
        int n = id >> 4, q = id & 15;
        uint4 w = *(const uint4*)(W2T + n * 128 + q * 8);
        *(uint4*)(smc + EW2T_OFF + n * 272 + q * 16) = w;
    }

    int e0 = blockIdx.x * TE;
    {
        int el = t >> 1;
        int jh = t & 1;
        int eg = e0 + el;
        int s = src[eg], d = dst[eg];
        unsigned long long eadup[12];
#pragma unroll
        for (int k = 0; k < 12; k++) eadup[k] = dup2(ea[(size_t)eg * 12 + k]);

        __syncthreads();   // weights staged before any W1es read (R12 race fix)

        const uint4* pl4 = (const uint4*)(Pl + (size_t)s * H);
        const uint4* pr4 = (const uint4*)(Pr + (size_t)d * H);
#pragma unroll
        for (int g = 0; g < 8; g++) {
            int grp = jh * 8 + g;
            uint4 a = pl4[grp];
            uint4 b = pr4[grp];
            float2 pa, pb;
            unsigned long long s01, s23, s45, s67;
            pa = h2f(a.x); pb = h2f(b.x); s01 = pk2(pa.x + pb.x, pa.y + pb.y);
            pa = h2f(a.y); pb = h2f(b.y); s23 = pk2(pa.x + pb.x, pa.y + pb.y);
            pa = h2f(a.z); pb = h2f(b.z); s45 = pk2(pa.x + pb.x, pa.y + pb.y);
            pa = h2f(a.w); pb = h2f(b.w); s67 = pk2(pa.x + pb.x, pa.y + pb.y);
            int jb = grp * 8;
#pragma unroll
            for (int k = 0; k < 12; k++) {
                ulonglong2 w0 = *(const ulonglong2*)&W1es[k * 128 + jb];
                ulonglong2 w1 = *(const ulonglong2*)&W1es[k * 128 + jb + 4];
                fma2(s01, w0.x, eadup[k]);
                fma2(s23, w0.y, eadup[k]);
                fma2(s45, w1.x, eadup[k]);
                fma2(s67, w1.y, eadup[k]);
            }
            float2 f01 = upk2(s01), f23 = upk2(s23), f45 = upk2(s45), f67 = upk2(s67);
            uint4 pkd;
            pkd.x = f2h2(fmaxf(f01.x, 0.f), fmaxf(f01.y, 0.f));
            pkd.y = f2h2(fmaxf(f23.x, 0.f), fmaxf(f23.y, 0.f));
            pkd.z = f2h2(fmaxf(f45.x, 0.f), fmaxf(f45.y, 0.f));
            pkd.w = f2h2(fmaxf(f67.x, 0.f), fmaxf(f67.y, 0.f));
            *(uint4*)(smc + EZ1_OFF + el * (ZST * 2) + jb * 2) = pkd;
        }
    }
    __syncthreads();

    int lane = t & 31, warp = t >> 5;
    int m0 = warp * 16;
    float acc[8][4];
#pragma unroll
    for (int nt = 0; nt < 8; nt++)
#pragma unroll
        for (int m = 0; m < 4; m++) acc[nt][m] = 0.f;

    uint32_t a_base = sb + EZ1_OFF + (uint32_t)(m0 + (lane & 15)) * (ZST * 2)
                      + (uint32_t)(lane >> 4) * 16;
    uint32_t b_base = sb + EW2T_OFF + (uint32_t)(lane & 7) * (ZST * 2)
                      + (uint32_t)((lane >> 3) & 1) * 16;

#pragma unroll
    for (int ks = 0; ks < 8; ks++) {
        uint32_t a0, a1, a2, a3;
        ldmA(a0, a1, a2, a3, a_base + ks * 32);
#pragma unroll
        for (int nt = 0; nt < 8; nt++) {
            uint32_t b0, b1v;
            ldmB(b0, b1v, b_base + (uint32_t)nt * 8 * (ZST * 2) + ks * 32);
            mma16816(acc[nt], a0, a1, a2, a3, b0, b1v);
        }
    }

    int qr = lane >> 2;
    int qc = (lane & 3) * 2;
    float p0 = 0.f, p1 = 0.f;
#pragma unroll
    for (int nt = 0; nt < 8; nt++) {
        int c0 = nt * 8 + qc, c1 = c0 + 1;
        float w30 = W3s[c0], w31 = W3s[c1];
        float bb0 = b2s[c0], bb1 = b2s[c1];
        p0 = fmaf(fmaxf(acc[nt][0] + bb0, 0.f), w30, p0);
        p0 = fmaf(fmaxf(acc[nt][1] + bb1, 0.f), w31, p0);
        p1 = fmaf(fmaxf(acc[nt][2] + bb0, 0.f), w30, p1);
        p1 = fmaf(fmaxf(acc[nt][3] + bb1, 0.f), w31, p1);
    }
    p0 += __shfl_xor_sync(0xffffffffu, p0, 1);
    p0 += __shfl_xor_sync(0xffffffffu, p0, 2);
    p1 += __shfl_xor_sync(0xffffffffu, p1, 1);
    p1 += __shfl_xor_sync(0xffffffffu, p1, 2);
    if ((lane & 3) == 0) {
        float b3v = b3[0];
        float x0 = p0 + b3v;
        float x1 = p1 + b3v;
        out[e0 + m0 + qr]     = fmaxf(x0, 0.f) + log1pf(expf(-fabsf(x0)));
        out[e0 + m0 + qr + 8] = fmaxf(x1, 0.f) + log1pf(expf(-fabsf(x1)));
    }
}

// ---------------- launch ----------------
extern "C" void kernel_launch(void* const* d_in, const int* in_sizes, int n_in,
                              void* d_out, int out_size) {
    const float* x      = (const float*)d_in[0];
    const int*   ei     = (const int*)d_in[1];
    const float* ea     = (const float*)d_in[2];
    const float* node_W = (const float*)d_in[3];
    const float* node_b = (const float*)d_in[4];
    const float* sWl    = (const float*)d_in[5];
    const float* sbl    = (const float*)d_in[6];
    const float* sWr    = (const float*)d_in[7];
    const float* ln_g   = (const float*)d_in[8];
    const float* ln_b   = (const float*)d_in[9];
    const float* W1     = (const float*)d_in[10];
    const float* b1     = (const float*)d_in[11];
    const float* W2     = (const float*)d_in[12];
    const float* b2     = (const float*)d_in[13];
    const float* W3     = (const float*)d_in[14];
    const float* b3     = (const float*)d_in[15];
    float* out = (float*)d_out;
    const int* src = ei;
    const int* dstp = ei + N_EDGES;

    __half *pA, *pB, *pPl, *pPr, *pWsT, *pW1T, *pW2T;
    int *pDegi, *pLoc, *pBsum, *pBoff, *pOff, *pCur, *pCsr;
    cudaGetSymbolAddress((void**)&pA, g_bufA);
    cudaGetSymbolAddress((void**)&pB, g_bufB);
    cudaGetSymbolAddress((void**)&pPl, g_Plh);
    cudaGetSymbolAddress((void**)&pPr, g_Prh);
    cudaGetSymbolAddress((void**)&pWsT, g_WsT);
    cudaGetSymbolAddress((void**)&pW1T, g_W1T);
    cudaGetSymbolAddress((void**)&pW2T, g_W2T);
    cudaGetSymbolAddress((void**)&pDegi, g_degi);
    cudaGetSymbolAddress((void**)&pLoc, g_loc);
    cudaGetSymbolAddress((void**)&pBsum, g_bsum);
    cudaGetSymbolAddress((void**)&pBoff, g_boff);
    cudaGetSymbolAddress((void**)&pOff, g_off);
    cudaGetSymbolAddress((void**)&pCur, g_cur);
    cudaGetSymbolAddress((void**)&pCsr, g_csr);

    // side stream + events (created once; host-side resources only)
    static cudaStream_t sB = nullptr;
    static cudaEvent_t evFork = nullptr, evJoin = nullptr;
    if (sB == nullptr) {
        cudaStreamCreateWithFlags(&sB, cudaStreamNonBlocking);
        cudaEventCreateWithFlags(&evFork, cudaEventDisableTiming);
        cudaEventCreateWithFlags(&evJoin, cudaEventDisableTiming);
    }

    // fork: CSR build chain on side stream, weight prep + node proj on main stream
    cudaEventRecord(evFork, 0);
    cudaStreamWaitEvent(sB, evFork, 0);

    cudaMemsetAsync(pDegi, 0, N_NODES * sizeof(int), sB);
    k_deg<<<(N_EDGES + 255) / 256, 256, 0, sB>>>(dstp, pDegi);
    k_scan1<<<NB, 256, 0, sB>>>(pDegi, pLoc, pBsum);
    k_scan2<<<1, 512, 0, sB>>>(pBsum, pBoff);
    k_scan3<<<(N_NODES + 255) / 256, 256, 0, sB>>>(pLoc, pBoff, pOff, pCur);
    k_csrfill<<<(N_EDGES + 255) / 256, 256, 0, sB>>>(src, dstp, pCur, pCsr);
    cudaEventRecord(evJoin, sB);

    k_wprep<<<(3 * 128 * 256 + 255) / 256, 256>>>(sWl, sWr, W1, W2, pWsT, pW1T, pW2T);
    k_nodeproj<<<(N_NODES * 16 + 255) / 256, 256>>>(x, node_W, node_b, pA);

    // join before first gather (needs off/csr)
    cudaStreamWaitEvent(0, evJoin, 0);

    cudaFuncSetAttribute(k_sage_mma, cudaFuncAttributeMaxDynamicSharedMemorySize, SG_SM);
    cudaFuncSetAttribute(k_plpr_mma, cudaFuncAttributeMaxDynamicSharedMemorySize, PP_SM);
    cudaFuncSetAttribute(k_edge, cudaFuncAttributeMaxDynamicSharedMemorySize, ESM_TOTAL);

    __half* hcur = pA;
    __half* other = pB;
    for (int l = 0; l < 3; l++) {
        k_gather<<<(N_NODES * 32 + 255) / 256, 256>>>(pOff, pCsr, hcur, other);
        k_sage_mma<<<(N_NODES + 127) / 128, 256, SG_SM>>>(
            hcur, other, pWsT + (size_t)l * 128 * 256, sbl + l * H,
            ln_g + l * H, ln_b + l * H);
        __half* tmp = hcur; hcur = other; other = tmp;
    }

    k_plpr_mma<<<(N_NODES + 63) / 64, 256, PP_SM>>>(hcur, pW1T, b1, pPl, pPr);

    k_edge<<<N_EDGES / TE, 512, ESM_TOTAL>>>(src, dstp, ea, pPl, pPr, W1, pW2T, b2, W3, b3, out);
}

// round 16
// speedup vs baseline: 1.5084x; 1.5084x over previous
#include <cuda_runtime.h>
#include <cuda_fp16.h>
#include <cstdint>

#define N_NODES 100000
#define N_EDGES 800000
#define H 128
#define HH (H*H)
#define NB ((N_NODES + 255) / 256)   // 391 scan blocks

// ---- scratch (no cudaMalloc allowed) ----
__device__ __half g_bufA[N_NODES * H];
__device__ __half g_bufB[N_NODES * H];
__device__ __half g_Plh[N_NODES * H];
__device__ __half g_Prh[N_NODES * H];
__device__ __half g_WsT[3 * H * 256];   // [l][n=128][k=256] : k<128 Wl^T, k>=128 Wr^T
__device__ __half g_W1T[256 * H];       // [n'=256][k=128]   : n'<128 Pl cols, else Pr
__device__ __half g_W2T[64 * H];        // [n=64][k=128] fp16 W2^T
// CSR scratch
__device__ int g_degi[N_NODES];
__device__ int g_loc[N_NODES];
__device__ int g_bsum[512];
__device__ int g_boff[512];
__device__ int g_off[N_NODES + 1];
__device__ int g_cur[N_NODES];
__device__ int g_csr[N_EDGES];

// ---- packed fp32x2 helpers ----
__device__ __forceinline__ unsigned long long pk2(float x, float y) {
    unsigned long long r;
    asm("mov.b64 %0, {%1, %2};" : "=l"(r) : "f"(x), "f"(y));
    return r;
}
__device__ __forceinline__ unsigned long long dup2(float x) { return pk2(x, x); }
__device__ __forceinline__ void fma2(unsigned long long& d, unsigned long long a,
                                     unsigned long long b) {
    asm("fma.rn.f32x2 %0, %1, %2, %0;" : "+l"(d) : "l"(a), "l"(b));
}
__device__ __forceinline__ float2 upk2(unsigned long long v) {
    float2 f;
    asm("mov.b64 {%0, %1}, %2;" : "=f"(f.x), "=f"(f.y) : "l"(v));
    return f;
}
// fp16 pack/unpack
__device__ __forceinline__ float2 h2f(unsigned int u) {
    __half2 h = *reinterpret_cast<__half2*>(&u);
    return __half22float2(h);
}
__device__ __forceinline__ unsigned int f2h2(float lo, float hi) {
    __half2 h = __floats2half2_rn(lo, hi);
    return *reinterpret_cast<unsigned int*>(&h);
}
__device__ __forceinline__ uint32_t smem_u32(const void* p) {
    uint32_t a;
    asm("{ .reg .u64 t; cvta.to.shared.u64 t, %1; cvt.u32.u64 %0, t; }" : "=r"(a) : "l"(p));
    return a;
}

// ---- mma helpers (verified R7..R13) ----
__device__ __forceinline__ void ldmA(uint32_t& a0, uint32_t& a1, uint32_t& a2, uint32_t& a3,
                                     uint32_t addr) {
    asm volatile("ldmatrix.sync.aligned.m8n8.x4.shared.b16 {%0,%1,%2,%3}, [%4];"
                 : "=r"(a0), "=r"(a1), "=r"(a2), "=r"(a3) : "r"(addr));
}
__device__ __forceinline__ void ldmB(uint32_t& b0, uint32_t& b1, uint32_t addr) {
    asm volatile("ldmatrix.sync.aligned.m8n8.x2.shared.b16 {%0,%1}, [%2];"
                 : "=r"(b0), "=r"(b1) : "r"(addr));
}
__device__ __forceinline__ void mma16816(float* c, uint32_t a0, uint32_t a1, uint32_t a2,
                                         uint32_t a3, uint32_t b0, uint32_t b1) {
    asm volatile(
        "mma.sync.aligned.m16n8k16.row.col.f32.f16.f16.f32 "
        "{%0,%1,%2,%3}, {%4,%5,%6,%7}, {%8,%9}, {%0,%1,%2,%3};"
        : "+f"(c[0]), "+f"(c[1]), "+f"(c[2]), "+f"(c[3])
        : "r"(a0), "r"(a1), "r"(a2), "r"(a3), "r"(b0), "r"(b1));
}

// ---------------- degree ----------------
__global__ void k_deg(const int* __restrict__ dst, int* __restrict__ degi) {
    int e = blockIdx.x * 256 + threadIdx.x;
    if (e < N_EDGES) atomicAdd(degi + dst[e], 1);
}

// ---------------- CSR build: block scan + fill ----------------
__global__ void k_scan1(const int* __restrict__ degi, int* __restrict__ loc,
                        int* __restrict__ bsum) {
    __shared__ int sm[256];
    int tid = threadIdx.x;
    int gid = blockIdx.x * 256 + tid;
    int v = (gid < N_NODES) ? degi[gid] : 0;
    sm[tid] = v;
    __syncthreads();
#pragma unroll
    for (int o = 1; o < 256; o <<= 1) {
        int y = (tid >= o) ? sm[tid - o] : 0;
        __syncthreads();
        sm[tid] += y;
        __syncthreads();
    }
    if (gid < N_NODES) loc[gid] = sm[tid] - v;
    if (tid == 255) bsum[blockIdx.x] = sm[255];
}
__global__ void k_scan2(const int* __restrict__ bsum, int* __restrict__ boff) {
    __shared__ int sm[512];
    int tid = threadIdx.x;
    int v = (tid < NB) ? bsum[tid] : 0;
    sm[tid] = v;
    __syncthreads();
#pragma unroll
    for (int o = 1; o < 512; o <<= 1) {
        int y = (tid >= o) ? sm[tid - o] : 0;
        __syncthreads();
        sm[tid] += y;
        __syncthreads();
    }
    if (tid < NB) boff[tid] = sm[tid] - v;
}
__global__ void k_scan3(const int* __restrict__ loc, const int* __restrict__ boff,
                        int* __restrict__ off, int* __restrict__ cur) {
    int gid = blockIdx.x * 256 + threadIdx.x;
    if (gid < N_NODES) {
        int o = loc[gid] + boff[gid >> 8];
        off[gid] = o;
        cur[gid] = o;
    }
    if (gid == 0) off[N_NODES] = N_EDGES;
}
__global__ void k_csrfill(const int* __restrict__ src, const int* __restrict__ dst,
                          int* __restrict__ cur, int* __restrict__ csr) {
    int e = blockIdx.x * 256 + threadIdx.x;
    if (e < N_EDGES) {
        int d = dst[e];
        int slot = atomicAdd(cur + d, 1);
        csr[slot] = src[e];
    }
}

// ---------------- weight prep: transposed fp16 copies (incl. W2^T) ----------------
__global__ void k_wprep(const float* __restrict__ sWl, const float* __restrict__ sWr,
                        const float* __restrict__ W1, const float* __restrict__ W2,
                        __half* __restrict__ WsT, __half* __restrict__ W1T,
                        __half* __restrict__ W2T) {
    int i = blockIdx.x * 256 + threadIdx.x;
    if (i < 3 * 128 * 256) {
        int l = i / (128 * 256);
        int rem = i - l * (128 * 256);
        int n = rem >> 8;
        int k = rem & 255;
        float v = (k < 128) ? sWl[l * HH + k * H + n] : sWr[l * HH + (k - 128) * H + n];
        WsT[i] = __float2half_rn(v);
    }
    if (i < 256 * 128) {
        int n = i >> 7, k = i & 127;
        float v = (n < 128) ? W1[k * H + n] : W1[(128 + k) * H + (n - 128)];
        W1T[i] = __float2half_rn(v);
    }
    if (i < 64 * 128) {
        int n = i >> 7, k = i & 127;
        W2T[i] = __float2half_rn(W2[k * 64 + n]);
    }
}

// ---------------- node projection -> fp16 h ----------------
__global__ void __launch_bounds__(256) k_nodeproj(
    const float* __restrict__ x, const float* __restrict__ W,
    const float* __restrict__ b, __half* __restrict__ h) {
    __shared__ float Ws[5 * 128];
    __shared__ float bs[128];
    int t = threadIdx.x;
    if (t < 128) bs[t] = b[t];
    for (int i = t; i < 640; i += 256) Ws[i] = W[i];
    __syncthreads();
    int id = blockIdx.x * 256 + t;
    int node = id >> 4;
    if (node >= N_NODES) return;
    int c0 = (id & 15) * 8;
    float xv[5];
#pragma unroll
    for (int k = 0; k < 5; k++) xv[k] = x[node * 5 + k];
    float a[8];
#pragma unroll
    for (int j = 0; j < 8; j++) a[j] = bs[c0 + j];
#pragma unroll
    for (int k = 0; k < 5; k++)
#pragma unroll
        for (int j = 0; j < 8; j++)
            a[j] = fmaf(xv[k], Ws[k * 128 + c0 + j], a[j]);
    uint4 o;
    o.x = f2h2(a[0], a[1]); o.y = f2h2(a[2], a[3]);
    o.z = f2h2(a[4], a[5]); o.w = f2h2(a[6], a[7]);
    *(uint4*)(h + (size_t)node * H + c0) = o;
}

// ---------------- CSR gather mean (inv fused from offsets; 2x unrolled) ------------
__global__ void k_gather(const int* __restrict__ off, const int* __restrict__ csr,
                         const __half* __restrict__ h, __half* __restrict__ agg) {
    int node = (blockIdx.x * blockDim.x + threadIdx.x) >> 5;
    int lane = threadIdx.x & 31;
    if (node >= N_NODES) return;
    int b = off[node], e = off[node + 1];
    float a0 = 0.f, a1 = 0.f, a2 = 0.f, a3 = 0.f;
    int i = b;
    for (; i + 1 < e; i += 2) {
        int s0 = csr[i], s1 = csr[i + 1];
        uint2 v0 = ((const uint2*)(h + (size_t)s0 * H))[lane];
        uint2 v1 = ((const uint2*)(h + (size_t)s1 * H))[lane];
        float2 f;
        f = h2f(v0.x); a0 += f.x; a1 += f.y;
        f = h2f(v0.y); a2 += f.x; a3 += f.y;
        f = h2f(v1.x); a0 += f.x; a1 += f.y;
        f = h2f(v1.y); a2 += f.x; a3 += f.y;
    }
    if (i < e) {
        int s0 = csr[i];
        uint2 v0 = ((const uint2*)(h + (size_t)s0 * H))[lane];
        float2 f;
        f = h2f(v0.x); a0 += f.x; a1 += f.y;
        f = h2f(v0.y); a2 += f.x; a3 += f.y;
    }
    float iv = (e > b) ? 1.f / (float)(e - b) : 0.f;
    uint2 o;
    o.x = f2h2(a0 * iv, a1 * iv);
    o.y = f2h2(a2 * iv, a3 * iv);
    ((uint2*)(agg + (size_t)node * H))[lane] = o;
}

// ---------------- SAGE on HMMA fp16 (verified R11/R13) ----------------
#define SG_AS 0            // 128*144 = 18432 B
#define SG_WS 18432        // 128*144 = 18432 B
#define SG_LN 36864        // 384 f32 = 1536 B
#define SG_SM 38400
__global__ void __launch_bounds__(256) k_sage_mma(
    const __half* __restrict__ hX, __half* __restrict__ aggY,
    const __half* __restrict__ WsTl, const float* __restrict__ bl,
    const float* __restrict__ lg, const float* __restrict__ lb)
{
    extern __shared__ char smc[];
    uint32_t sb = smem_u32(smc);
    int t = threadIdx.x, lane = t & 31, warp = t >> 5;
    int row0 = blockIdx.x * 128;
    float* lns = (float*)(smc + SG_LN);
    if (t < 128) { lns[t] = bl[t]; lns[128 + t] = lg[t]; lns[256 + t] = lb[t]; }

    float acc[16][4];
#pragma unroll
    for (int nt = 0; nt < 16; nt++)
#pragma unroll
        for (int m = 0; m < 4; m++) acc[nt][m] = 0.f;

    for (int c = 0; c < 4; c++) {
        const __half* Usrc = (c < 2) ? aggY : hX;
        int kcol = (c & 1) * 64;
        __syncthreads();
#pragma unroll
        for (int p = 0; p < 8; p++) {
            int id = t + p * 256;
            int r = id >> 4, fq = id & 15;
            int row = row0 + r;
            uint2 v = make_uint2(0u, 0u);
            if (row < N_NODES)
                v = *(const uint2*)(Usrc + (size_t)row * H + kcol + fq * 4);
            *(uint2*)(smc + SG_AS + r * 144 + fq * 8) = v;
        }
#pragma unroll
        for (int p = 0; p < 4; p++) {
            int id = t + p * 256;
            int n = id >> 3, q = id & 7;
            uint4 w = *(const uint4*)(WsTl + n * 256 + c * 64 + q * 8);
            *(uint4*)(smc + SG_WS + n * 144 + q * 16) = w;
        }
        __syncthreads();
        uint32_t a_base = sb + SG_AS + (uint32_t)(warp * 16 + (lane & 15)) * 144
                          + (uint32_t)(lane >> 4) * 16;
        uint32_t b_base = sb + SG_WS + (uint32_t)(lane & 7) * 144
                          + (uint32_t)((lane >> 3) & 1) * 16;
#pragma unroll
        for (int ks = 0; ks < 4; ks++) {
            uint32_t a0, a1, a2, a3;
            ldmA(a0, a1, a2, a3, a_base + ks * 32);
#pragma unroll
            for (int nt = 0; nt < 16; nt++) {
                uint32_t b0, b1;
                ldmB(b0, b1, b_base + (uint32_t)nt * 8 * 144 + ks * 32);
                mma16816(acc[nt], a0, a1, a2, a3, b0, b1);
            }
        }
    }

    int qr = lane >> 2, qc = (lane & 3) * 2;
    int r0 = row0 + warp * 16 + qr;
    int r1 = r0 + 8;
    float s0 = 0.f, s1 = 0.f;
#pragma unroll
    for (int nt = 0; nt < 16; nt++) {
        int c0 = nt * 8 + qc;
        float bb0 = lns[c0], bb1 = lns[c0 + 1];
        acc[nt][0] += bb0; acc[nt][1] += bb1;
        acc[nt][2] += bb0; acc[nt][3] += bb1;
        s0 += acc[nt][0] + acc[nt][1];
        s1 += acc[nt][2] + acc[nt][3];
    }
    s0 += __shfl_xor_sync(0xffffffffu, s0, 1);
    s0 += __shfl_xor_sync(0xffffffffu, s0, 2);
    s1 += __shfl_xor_sync(0xffffffffu, s1, 1);
    s1 += __shfl_xor_sync(0xffffffffu, s1, 2);
    float mu0 = s0 * (1.f / 128.f), mu1 = s1 * (1.f / 128.f);
    float q0 = 0.f, q1 = 0.f;
#pragma unroll
    for (int nt = 0; nt < 16; nt++) {
        float d0 = acc[nt][0] - mu0, d1 = acc[nt][1] - mu0;
        float d2 = acc[nt][2] - mu1, d3 = acc[nt][3] - mu1;
        q0 = fmaf(d0, d0, q0); q0 = fmaf(d1, d1, q0);
        q1 = fmaf(d2, d2, q1); q1 = fmaf(d3, d3, q1);
    }
    q0 += __shfl_xor_sync(0xffffffffu, q0, 1);
    q0 += __shfl_xor_sync(0xffffffffu, q0, 2);
    q1 += __shfl_xor_sync(0xffffffffu, q1, 1);
    q1 += __shfl_xor_sync(0xffffffffu, q1, 2);
    float rs0 = rsqrtf(q0 * (1.f / 128.f) + 1e-5f);
    float rs1 = rsqrtf(q1 * (1.f / 128.f) + 1e-5f);
#pragma unroll
    for (int nt = 0; nt < 16; nt++) {
        int c0 = nt * 8 + qc;
        float g0 = lns[128 + c0], g1 = lns[128 + c0 + 1];
        float o0 = lns[256 + c0], o1 = lns[256 + c0 + 1];
        if (r0 < N_NODES) {
            *(unsigned*)(aggY + (size_t)r0 * H + c0) = f2h2(
                fmaxf(fmaf((acc[nt][0] - mu0) * rs0, g0, o0), 0.f),
                fmaxf(fmaf((acc[nt][1] - mu0) * rs0, g1, o1), 0.f));
        }
        if (r1 < N_NODES) {
            *(unsigned*)(aggY + (size_t)r1 * H + c0) = f2h2(
                fmaxf(fmaf((acc[nt][2] - mu1) * rs1, g0, o0), 0.f),
                fmaxf(fmaf((acc[nt][3] - mu1) * rs1, g1, o1), 0.f));
        }
    }
}

// ---------------- Pl/Pr on HMMA fp16 (verified R10-R13) ----------------
#define PP_AS 0            // 64*272 = 17408 B
#define PP_WS 17408        // 256*272 = 69632 B
#define PP_B1 87040        // 128 f32
#define PP_SM 87552
__global__ void __launch_bounds__(256) k_plpr_mma(
    const __half* __restrict__ h, const __half* __restrict__ W1T,
    const float* __restrict__ b1,
    __half* __restrict__ Pl, __half* __restrict__ Pr)
{
    extern __shared__ char smc[];
    uint32_t sb = smem_u32(smc);
    int t = threadIdx.x, lane = t & 31, warp = t >> 5;
    int row0 = blockIdx.x * 64;
    int half_ = warp >> 2;
    int wm = warp & 3;
    float* b1s = (float*)(smc + PP_B1);
    if (t < 128) b1s[t] = b1[t];

#pragma unroll
    for (int p = 0; p < 4; p++) {
        int id = t + p * 256;
        int r = id >> 4, fq = id & 15;
        int row = row0 + r;
        uint4 v = make_uint4(0u, 0u, 0u, 0u);
        if (row < N_NODES)
            v = *(const uint4*)(h + (size_t)row * H + fq * 8);
        *(uint4*)(smc + PP_AS + r * 272 + fq * 16) = v;
    }
#pragma unroll
    for (int p = 0; p < 16; p++) {
        int id = t + p * 256;
        int n = id >> 4, q = id & 15;
        uint4 w = *(const uint4*)(W1T + n * 128 + q * 8);
        *(uint4*)(smc + PP_WS + n * 272 + q * 16) = w;
    }
    __syncthreads();

    float acc[16][4];
#pragma unroll
    for (int nt = 0; nt < 16; nt++)
#pragma unroll
        for (int m = 0; m < 4; m++) acc[nt][m] = 0.f;

    uint32_t a_base = sb + PP_AS + (uint32_t)(wm * 16 + (lane & 15)) * 272
                      + (uint32_t)(lane >> 4) * 16;
    uint32_t b_base = sb + PP_WS + (uint32_t)half_ * 128 * 272
                      + (uint32_t)(lane & 7) * 272 + (uint32_t)((lane >> 3) & 1) * 16;
#pragma unroll
    for (int ks = 0; ks < 8; ks++) {
        uint32_t a0, a1, a2, a3;
        ldmA(a0, a1, a2, a3, a_base + ks * 32);
#pragma unroll
        for (int nt = 0; nt < 16; nt++) {
            uint32_t b0, b1v;
            ldmB(b0, b1v, b_base + (uint32_t)nt * 8 * 272 + ks * 32);
            mma16816(acc[nt], a0, a1, a2, a3, b0, b1v);
        }
    }

    int qr = lane >> 2, qc = (lane & 3) * 2;
    int r0 = row0 + wm * 16 + qr;
    int r1 = r0 + 8;
    __half* outp = half_ ? Pr : Pl;
#pragma unroll
    for (int nt = 0; nt < 16; nt++) {
        int c0 = nt * 8 + qc;
        float add0 = half_ ? 0.f : b1s[c0];
        float add1 = half_ ? 0.f : b1s[c0 + 1];
        if (r0 < N_NODES)
            *(unsigned*)(outp + (size_t)r0 * H + c0) = f2h2(acc[nt][0] + add0, acc[nt][1] + add1);
        if (r1 < N_NODES)
            *(unsigned*)(outp + (size_t)r1 * H + c0) = f2h2(acc[nt][2] + add0, acc[nt][3] + add1);
    }
}

// ---------------- fused edge MLP; TE=256, 512 threads (verified R13) ----------------
#define TE 256
#define ZST 136
#define EZ1_OFF   0                        // 256*272 = 69632
#define EW2T_OFF  69632                    // 64*272  = 17408
#define EW1_OFF   87040                    // 12*128 f32 = 6144
#define EW3_OFF   93184                    // 64 f32
#define EB2_OFF   93440                    // 64 f32
#define ESM_TOTAL 93696

__global__ void __launch_bounds__(512) k_edge(
    const int* __restrict__ src, const int* __restrict__ dst,
    const float* __restrict__ ea, const __half* __restrict__ Pl,
    const __half* __restrict__ Pr, const float* __restrict__ W1,
    const __half* __restrict__ W2T, const float* __restrict__ b2,
    const float* __restrict__ W3, const float* __restrict__ b3,
    float* __restrict__ out)
{
    extern __shared__ char smc[];
    uint32_t sb = smem_u32(smc);

    float* W1es = (float*)(smc + EW1_OFF);
    float* W3s  = (float*)(smc + EW3_OFF);
    float* b2s  = (float*)(smc + EB2_OFF);

    int t = threadIdx.x;

    for (int i = t; i < 12 * 128 / 4; i += 512)
        ((float4*)W1es)[i] = ((const float4*)(W1 + 256 * H))[i];
    if (t < 64) { W3s[t] = W3[t]; b2s[t] = b2[t]; }
#pragma unroll
    for (int p = 0; p < 2; p++) {
        int id = t + p * 512;
        int n = id >> 4, q = id & 15;
        uint4 w = *(const uint4*)(W2T + n * 128 + q * 8);
        *(uint4*)(smc + EW2T_OFF + n * 272 + q * 16) = w;
    }

    int e0 = blockIdx.x * TE;
    {
        int el = t >> 1;
        int jh = t & 1;
        int eg = e0 + el;
        int s = src[eg], d = dst[eg];
        unsigned long long eadup[12];
#pragma unroll
        for (int k = 0; k < 12; k++) eadup[k] = dup2(ea[(size_t)eg * 12 + k]);

        __syncthreads();   // weights staged before any W1es read (R12 race fix)

        const uint4* pl4 = (const uint4*)(Pl + (size_t)s * H);
        const uint4* pr4 = (const uint4*)(Pr + (size_t)d * H);
#pragma unroll
        for (int g = 0; g < 8; g++) {
            int grp = jh * 8 + g;
            uint4 a = pl4[grp];
            uint4 b = pr4[grp];
            float2 pa, pb;
            unsigned long long s01, s23, s45, s67;
            pa = h2f(a.x); pb = h2f(b.x); s01 = pk2(pa.x + pb.x, pa.y + pb.y);
            pa = h2f(a.y); pb = h2f(b.y); s23 = pk2(pa.x + pb.x, pa.y + pb.y);
            pa = h2f(a.z); pb = h2f(b.z); s45 = pk2(pa.x + pb.x, pa.y + pb.y);
            pa = h2f(a.w); pb = h2f(b.w); s67 = pk2(pa.x + pb.x, pa.y + pb.y);
            int jb = grp * 8;
#pragma unroll
            for (int k = 0; k < 12; k++) {
                ulonglong2 w0 = *(const ulonglong2*)&W1es[k * 128 + jb];
                ulonglong2 w1 = *(const ulonglong2*)&W1es[k * 128 + jb + 4];
                fma2(s01, w0.x, eadup[k]);
                fma2(s23, w0.y, eadup[k]);
                fma2(s45, w1.x, eadup[k]);
                fma2(s67, w1.y, eadup[k]);
            }
            float2 f01 = upk2(s01), f23 = upk2(s23), f45 = upk2(s45), f67 = upk2(s67);
            uint4 pkd;
            pkd.x = f2h2(fmaxf(f01.x, 0.f), fmaxf(f01.y, 0.f));
            pkd.y = f2h2(fmaxf(f23.x, 0.f), fmaxf(f23.y, 0.f));
            pkd.z = f2h2(fmaxf(f45.x, 0.f), fmaxf(f45.y, 0.f));
            pkd.w = f2h2(fmaxf(f67.x, 0.f), fmaxf(f67.y, 0.f));
            *(uint4*)(smc + EZ1_OFF + el * (ZST * 2) + jb * 2) = pkd;
        }
    }
    __syncthreads();

    int lane = t & 31, warp = t >> 5;
    int m0 = warp * 16;
    float acc[8][4];
#pragma unroll
    for (int nt = 0; nt < 8; nt++)
#pragma unroll
        for (int m = 0; m < 4; m++) acc[nt][m] = 0.f;

    uint32_t a_base = sb + EZ1_OFF + (uint32_t)(m0 + (lane & 15)) * (ZST * 2)
                      + (uint32_t)(lane >> 4) * 16;
    uint32_t b_base = sb + EW2T_OFF + (uint32_t)(lane & 7) * (ZST * 2)
                      + (uint32_t)((lane >> 3) & 1) * 16;

#pragma unroll
    for (int ks = 0; ks < 8; ks++) {
        uint32_t a0, a1, a2, a3;
        ldmA(a0, a1, a2, a3, a_base + ks * 32);
#pragma unroll
        for (int nt = 0; nt < 8; nt++) {
            uint32_t b0, b1v;
            ldmB(b0, b1v, b_base + (uint32_t)nt * 8 * (ZST * 2) + ks * 32);
            mma16816(acc[nt], a0, a1, a2, a3, b0, b1v);
        }
    }

    int qr = lane >> 2;
    int qc = (lane & 3) * 2;
    float p0 = 0.f, p1 = 0.f;
#pragma unroll
    for (int nt = 0; nt < 8; nt++) {
        int c0 = nt * 8 + qc, c1 = c0 + 1;
        float w30 = W3s[c0], w31 = W3s[c1];
        float bb0 = b2s[c0], bb1 = b2s[c1];
        p0 = fmaf(fmaxf(acc[nt][0] + bb0, 0.f), w30, p0);
        p0 = fmaf(fmaxf(acc[nt][1] + bb1, 0.f), w31, p0);
        p1 = fmaf(fmaxf(acc[nt][2] + bb0, 0.f), w30, p1);
        p1 = fmaf(fmaxf(acc[nt][3] + bb1, 0.f), w31, p1);
    }
    p0 += __shfl_xor_sync(0xffffffffu, p0, 1);
    p0 += __shfl_xor_sync(0xffffffffu, p0, 2);
    p1 += __shfl_xor_sync(0xffffffffu, p1, 1);
    p1 += __shfl_xor_sync(0xffffffffu, p1, 2);
    if ((lane & 3) == 0) {
        float b3v = b3[0];
        float x0 = p0 + b3v;
        float x1 = p1 + b3v;
        out[e0 + m0 + qr]     = fmaxf(x0, 0.f) + log1pf(expf(-fabsf(x0)));
        out[e0 + m0 + qr + 8] = fmaxf(x1, 0.f) + log1pf(expf(-fabsf(x1)));
    }
}

// ---------------- launch (single stream, verified R13 ordering) ----------------
extern "C" void kernel_launch(void* const* d_in, const int* in_sizes, int n_in,
                              void* d_out, int out_size) {
    const float* x      = (const float*)d_in[0];
    const int*   ei     = (const int*)d_in[1];
    const float* ea     = (const float*)d_in[2];
    const float* node_W = (const float*)d_in[3];
    const float* node_b = (const float*)d_in[4];
    const float* sWl    = (const float*)d_in[5];
    const float* sbl    = (const float*)d_in[6];
    const float* sWr    = (const float*)d_in[7];
    const float* ln_g   = (const float*)d_in[8];
    const float* ln_b   = (const float*)d_in[9];
    const float* W1     = (const float*)d_in[10];
    const float* b1     = (const float*)d_in[11];
    const float* W2     = (const float*)d_in[12];
    const float* b2     = (const float*)d_in[13];
    const float* W3     = (const float*)d_in[14];
    const float* b3     = (const float*)d_in[15];
    float* out = (float*)d_out;
    const int* src = ei;
    const int* dstp = ei + N_EDGES;

    __half *pA, *pB, *pPl, *pPr, *pWsT, *pW1T, *pW2T;
    int *pDegi, *pLoc, *pBsum, *pBoff, *pOff, *pCur, *pCsr;
    cudaGetSymbolAddress((void**)&pA, g_bufA);
    cudaGetSymbolAddress((void**)&pB, g_bufB);
    cudaGetSymbolAddress((void**)&pPl, g_Plh);
    cudaGetSymbolAddress((void**)&pPr, g_Prh);
    cudaGetSymbolAddress((void**)&pWsT, g_WsT);
    cudaGetSymbolAddress((void**)&pW1T, g_W1T);
    cudaGetSymbolAddress((void**)&pW2T, g_W2T);
    cudaGetSymbolAddress((void**)&pDegi, g_degi);
    cudaGetSymbolAddress((void**)&pLoc, g_loc);
    cudaGetSymbolAddress((void**)&pBsum, g_bsum);
    cudaGetSymbolAddress((void**)&pBoff, g_boff);
    cudaGetSymbolAddress((void**)&pOff, g_off);
    cudaGetSymbolAddress((void**)&pCur, g_cur);
    cudaGetSymbolAddress((void**)&pCsr, g_csr);

    // CSR build
    cudaMemsetAsync(pDegi, 0, N_NODES * sizeof(int));
    k_deg<<<(N_EDGES + 255) / 256, 256>>>(dstp, pDegi);
    k_scan1<<<NB, 256>>>(pDegi, pLoc, pBsum);
    k_scan2<<<1, 512>>>(pBsum, pBoff);
    k_scan3<<<(N_NODES + 255) / 256, 256>>>(pLoc, pBoff, pOff, pCur);
    k_csrfill<<<(N_EDGES + 255) / 256, 256>>>(src, dstp, pCur, pCsr);

    k_wprep<<<(3 * 128 * 256 + 255) / 256, 256>>>(sWl, sWr, W1, W2, pWsT, pW1T, pW2T);
    k_nodeproj<<<(N_NODES * 16 + 255) / 256, 256>>>(x, node_W, node_b, pA);

    cudaFuncSetAttribute(k_sage_mma, cudaFuncAttributeMaxDynamicSharedMemorySize, SG_SM);
    cudaFuncSetAttribute(k_plpr_mma, cudaFuncAttributeMaxDynamicSharedMemorySize, PP_SM);
    cudaFuncSetAttribute(k_edge, cudaFuncAttributeMaxDynamicSharedMemorySize, ESM_TOTAL);

    __half* hcur = pA;
    __half* other = pB;
    for (int l = 0; l < 3; l++) {
        k_gather<<<(N_NODES * 32 + 255) / 256, 256>>>(pOff, pCsr, hcur, other);
        k_sage_mma<<<(N_NODES + 127) / 128, 256, SG_SM>>>(
            hcur, other, pWsT + (size_t)l * 128 * 256, sbl + l * H,
            ln_g + l * H, ln_b + l * H);
        __half* tmp = hcur; hcur = other; other = tmp;
    }

    k_plpr_mma<<<(N_NODES + 63) / 64, 256, PP_SM>>>(hcur, pW1T, b1, pPl, pPr);

    k_edge<<<N_EDGES / TE, 512, ESM_TOTAL>>>(src, dstp, ea, pPl, pPr, W1, pW2T, b2, W3, b3, out);
}

// round 17
// speedup vs baseline: 1.5944x; 1.0571x over previous
#include <cuda_runtime.h>
#include <cuda_fp16.h>
#include <cstdint>

#define N_NODES 100000
#define N_EDGES 800000
#define H 128
#define HH (H*H)
#define NB ((N_NODES + 255) / 256)   // 391 scan blocks

// ---- scratch (no cudaMalloc allowed) ----
__device__ __half g_bufA[N_NODES * H];
__device__ __half g_bufB[N_NODES * H];
__device__ __half g_Plh[N_NODES * H];
__device__ __half g_Prh[N_NODES * H];
__device__ __half g_WsT[3 * H * 256];   // [l][n=128][k=256]
__device__ __half g_W1T[256 * H];       // [n'=256][k=128]
__device__ __half g_W2T[64 * H];        // [n=64][k=128]
__device__ __half g_W1eT[128 * 16];     // [n=128][k=16] (k>=12 zero)
// CSR scratch
__device__ int g_degi[N_NODES];
__device__ int g_loc[N_NODES];
__device__ int g_bsum[512];
__device__ int g_boff[512];
__device__ int g_off[N_NODES + 1];
__device__ int g_cur[N_NODES];
__device__ int g_csr[N_EDGES];

// ---- fp16 pack/unpack ----
__device__ __forceinline__ float2 h2f(unsigned int u) {
    __half2 h = *reinterpret_cast<__half2*>(&u);
    return __half22float2(h);
}
__device__ __forceinline__ unsigned int f2h2(float lo, float hi) {
    __half2 h = __floats2half2_rn(lo, hi);
    return *reinterpret_cast<unsigned int*>(&h);
}
__device__ __forceinline__ uint32_t smem_u32(const void* p) {
    uint32_t a;
    asm("{ .reg .u64 t; cvta.to.shared.u64 t, %1; cvt.u32.u64 %0, t; }" : "=r"(a) : "l"(p));
    return a;
}
__device__ __forceinline__ unsigned int hadd3_relu(unsigned int a, unsigned int b,
                                                   unsigned int c) {
    __half2 s = __hadd2(__hadd2(*(__half2*)&a, *(__half2*)&b), *(__half2*)&c);
    __half2 z = __float2half2_rn(0.f);
    __half2 r = __hmax2(s, z);
    return *(unsigned int*)&r;
}

// ---- mma helpers (verified R7..R16) ----
__device__ __forceinline__ void ldmA(uint32_t& a0, uint32_t& a1, uint32_t& a2, uint32_t& a3,
                                     uint32_t addr) {
    asm volatile("ldmatrix.sync.aligned.m8n8.x4.shared.b16 {%0,%1,%2,%3}, [%4];"
                 : "=r"(a0), "=r"(a1), "=r"(a2), "=r"(a3) : "r"(addr));
}
__device__ __forceinline__ void ldmB(uint32_t& b0, uint32_t& b1, uint32_t addr) {
    asm volatile("ldmatrix.sync.aligned.m8n8.x2.shared.b16 {%0,%1}, [%2];"
                 : "=r"(b0), "=r"(b1) : "r"(addr));
}
__device__ __forceinline__ void mma16816(float* c, uint32_t a0, uint32_t a1, uint32_t a2,
                                         uint32_t a3, uint32_t b0, uint32_t b1) {
    asm volatile(
        "mma.sync.aligned.m16n8k16.row.col.f32.f16.f16.f32 "
        "{%0,%1,%2,%3}, {%4,%5,%6,%7}, {%8,%9}, {%0,%1,%2,%3};"
        : "+f"(c[0]), "+f"(c[1]), "+f"(c[2]), "+f"(c[3])
        : "r"(a0), "r"(a1), "r"(a2), "r"(a3), "r"(b0), "r"(b1));
}

// ---------------- degree ----------------
__global__ void k_deg(const int* __restrict__ dst, int* __restrict__ degi) {
    int e = blockIdx.x * 256 + threadIdx.x;
    if (e < N_EDGES) atomicAdd(degi + dst[e], 1);
}

// ---------------- CSR build ----------------
__global__ void k_scan1(const int* __restrict__ degi, int* __restrict__ loc,
                        int* __restrict__ bsum) {
    __shared__ int sm[256];
    int tid = threadIdx.x;
    int gid = blockIdx.x * 256 + tid;
    int v = (gid < N_NODES) ? degi[gid] : 0;
    sm[tid] = v;
    __syncthreads();
#pragma unroll
    for (int o = 1; o < 256; o <<= 1) {
        int y = (tid >= o) ? sm[tid - o] : 0;
        __syncthreads();
        sm[tid] += y;
        __syncthreads();
    }
    if (gid < N_NODES) loc[gid] = sm[tid] - v;
    if (tid == 255) bsum[blockIdx.x] = sm[255];
}
__global__ void k_scan2(const int* __restrict__ bsum, int* __restrict__ boff) {
    __shared__ int sm[512];
    int tid = threadIdx.x;
    int v = (tid < NB) ? bsum[tid] : 0;
    sm[tid] = v;
    __syncthreads();
#pragma unroll
    for (int o = 1; o < 512; o <<= 1) {
        int y = (tid >= o) ? sm[tid - o] : 0;
        __syncthreads();
        sm[tid] += y;
        __syncthreads();
    }
    if (tid < NB) boff[tid] = sm[tid] - v;
}
__global__ void k_scan3(const int* __restrict__ loc, const int* __restrict__ boff,
                        int* __restrict__ off, int* __restrict__ cur) {
    int gid = blockIdx.x * 256 + threadIdx.x;
    if (gid < N_NODES) {
        int o = loc[gid] + boff[gid >> 8];
        off[gid] = o;
        cur[gid] = o;
    }
    if (gid == 0) off[N_NODES] = N_EDGES;
}
__global__ void k_csrfill(const int* __restrict__ src, const int* __restrict__ dst,
                          int* __restrict__ cur, int* __restrict__ csr) {
    int e = blockIdx.x * 256 + threadIdx.x;
    if (e < N_EDGES) {
        int d = dst[e];
        int slot = atomicAdd(cur + d, 1);
        csr[slot] = src[e];
    }
}

// ---------------- weight prep (adds W1eT) ----------------
__global__ void k_wprep(const float* __restrict__ sWl, const float* __restrict__ sWr,
                        const float* __restrict__ W1, const float* __restrict__ W2,
                        __half* __restrict__ WsT, __half* __restrict__ W1T,
                        __half* __restrict__ W2T, __half* __restrict__ W1eT) {
    int i = blockIdx.x * 256 + threadIdx.x;
    if (i < 3 * 128 * 256) {
        int l = i / (128 * 256);
        int rem = i - l * (128 * 256);
        int n = rem >> 8;
        int k = rem & 255;
        float v = (k < 128) ? sWl[l * HH + k * H + n] : sWr[l * HH + (k - 128) * H + n];
        WsT[i] = __float2half_rn(v);
    }
    if (i < 256 * 128) {
        int n = i >> 7, k = i & 127;
        float v = (n < 128) ? W1[k * H + n] : W1[(128 + k) * H + (n - 128)];
        W1T[i] = __float2half_rn(v);
    }
    if (i < 64 * 128) {
        int n = i >> 7, k = i & 127;
        W2T[i] = __float2half_rn(W2[k * 64 + n]);
    }
    if (i < 128 * 16) {
        int n = i >> 4, k = i & 15;
        float v = (k < 12) ? W1[(256 + k) * H + n] : 0.f;
        W1eT[i] = __float2half_rn(v);
    }
}

// ---------------- node projection -> fp16 h ----------------
__global__ void __launch_bounds__(256) k_nodeproj(
    const float* __restrict__ x, const float* __restrict__ W,
    const float* __restrict__ b, __half* __restrict__ h) {
    __shared__ float Ws[5 * 128];
    __shared__ float bs[128];
    int t = threadIdx.x;
    if (t < 128) bs[t] = b[t];
    for (int i = t; i < 640; i += 256) Ws[i] = W[i];
    __syncthreads();
    int id = blockIdx.x * 256 + t;
    int node = id >> 4;
    if (node >= N_NODES) return;
    int c0 = (id & 15) * 8;
    float xv[5];
#pragma unroll
    for (int k = 0; k < 5; k++) xv[k] = x[node * 5 + k];
    float a[8];
#pragma unroll
    for (int j = 0; j < 8; j++) a[j] = bs[c0 + j];
#pragma unroll
    for (int k = 0; k < 5; k++)
#pragma unroll
        for (int j = 0; j < 8; j++)
            a[j] = fmaf(xv[k], Ws[k * 128 + c0 + j], a[j]);
    uint4 o;
    o.x = f2h2(a[0], a[1]); o.y = f2h2(a[2], a[3]);
    o.z = f2h2(a[4], a[5]); o.w = f2h2(a[6], a[7]);
    *(uint4*)(h + (size_t)node * H + c0) = o;
}

// ---------------- CSR gather mean (verified R16) ----------------
__global__ void k_gather(const int* __restrict__ off, const int* __restrict__ csr,
                         const __half* __restrict__ h, __half* __restrict__ agg) {
    int node = (blockIdx.x * blockDim.x + threadIdx.x) >> 5;
    int lane = threadIdx.x & 31;
    if (node >= N_NODES) return;
    int b = off[node], e = off[node + 1];
    float a0 = 0.f, a1 = 0.f, a2 = 0.f, a3 = 0.f;
    int i = b;
    for (; i + 1 < e; i += 2) {
        int s0 = csr[i], s1 = csr[i + 1];
        uint2 v0 = ((const uint2*)(h + (size_t)s0 * H))[lane];
        uint2 v1 = ((const uint2*)(h + (size_t)s1 * H))[lane];
        float2 f;
        f = h2f(v0.x); a0 += f.x; a1 += f.y;
        f = h2f(v0.y); a2 += f.x; a3 += f.y;
        f = h2f(v1.x); a0 += f.x; a1 += f.y;
        f = h2f(v1.y); a2 += f.x; a3 += f.y;
    }
    if (i < e) {
        int s0 = csr[i];
        uint2 v0 = ((const uint2*)(h + (size_t)s0 * H))[lane];
        float2 f;
        f = h2f(v0.x); a0 += f.x; a1 += f.y;
        f = h2f(v0.y); a2 += f.x; a3 += f.y;
    }
    float iv = (e > b) ? 1.f / (float)(e - b) : 0.f;
    uint2 o;
    o.x = f2h2(a0 * iv, a1 * iv);
    o.y = f2h2(a2 * iv, a3 * iv);
    ((uint2*)(agg + (size_t)node * H))[lane] = o;
}

// ---------------- SAGE on HMMA fp16 (verified R11/R13/R16) ----------------
#define SG_AS 0
#define SG_WS 18432
#define SG_LN 36864
#define SG_SM 38400
__global__ void __launch_bounds__(256) k_sage_mma(
    const __half* __restrict__ hX, __half* __restrict__ aggY,
    const __half* __restrict__ WsTl, const float* __restrict__ bl,
    const float* __restrict__ lg, const float* __restrict__ lb)
{
    extern __shared__ char smc[];
    uint32_t sb = smem_u32(smc);
    int t = threadIdx.x, lane = t & 31, warp = t >> 5;
    int row0 = blockIdx.x * 128;
    float* lns = (float*)(smc + SG_LN);
    if (t < 128) { lns[t] = bl[t]; lns[128 + t] = lg[t]; lns[256 + t] = lb[t]; }

    float acc[16][4];
#pragma unroll
    for (int nt = 0; nt < 16; nt++)
#pragma unroll
        for (int m = 0; m < 4; m++) acc[nt][m] = 0.f;

    for (int c = 0; c < 4; c++) {
        const __half* Usrc = (c < 2) ? aggY : hX;
        int kcol = (c & 1) * 64;
        __syncthreads();
#pragma unroll
        for (int p = 0; p < 8; p++) {
            int id = t + p * 256;
            int r = id >> 4, fq = id & 15;
            int row = row0 + r;
            uint2 v = make_uint2(0u, 0u);
            if (row < N_NODES)
                v = *(const uint2*)(Usrc + (size_t)row * H + kcol + fq * 4);
            *(uint2*)(smc + SG_AS + r * 144 + fq * 8) = v;
        }
#pragma unroll
        for (int p = 0; p < 4; p++) {
            int id = t + p * 256;
            int n = id >> 3, q = id & 7;
            uint4 w = *(const uint4*)(WsTl + n * 256 + c * 64 + q * 8);
            *(uint4*)(smc + SG_WS + n * 144 + q * 16) = w;
        }
        __syncthreads();
        uint32_t a_base = sb + SG_AS + (uint32_t)(warp * 16 + (lane & 15)) * 144
                          + (uint32_t)(lane >> 4) * 16;
        uint32_t b_base = sb + SG_WS + (uint32_t)(lane & 7) * 144
                          + (uint32_t)((lane >> 3) & 1) * 16;
#pragma unroll
        for (int ks = 0; ks < 4; ks++) {
            uint32_t a0, a1, a2, a3;
            ldmA(a0, a1, a2, a3, a_base + ks * 32);
#pragma unroll
            for (int nt = 0; nt < 16; nt++) {
                uint32_t b0, b1;
                ldmB(b0, b1, b_base + (uint32_t)nt * 8 * 144 + ks * 32);
                mma16816(acc[nt], a0, a1, a2, a3, b0, b1);
            }
        }
    }

    int qr = lane >> 2, qc = (lane & 3) * 2;
    int r0 = row0 + warp * 16 + qr;
    int r1 = r0 + 8;
    float s0 = 0.f, s1 = 0.f;
#pragma unroll
    for (int nt = 0; nt < 16; nt++) {
        int c0 = nt * 8 + qc;
        float bb0 = lns[c0], bb1 = lns[c0 + 1];
        acc[nt][0] += bb0; acc[nt][1] += bb1;
        acc[nt][2] += bb0; acc[nt][3] += bb1;
        s0 += acc[nt][0] + acc[nt][1];
        s1 += acc[nt][2] + acc[nt][3];
    }
    s0 += __shfl_xor_sync(0xffffffffu, s0, 1);
    s0 += __shfl_xor_sync(0xffffffffu, s0, 2);
    s1 += __shfl_xor_sync(0xffffffffu, s1, 1);
    s1 += __shfl_xor_sync(0xffffffffu, s1, 2);
    float mu0 = s0 * (1.f / 128.f), mu1 = s1 * (1.f / 128.f);
    float q0 = 0.f, q1 = 0.f;
#pragma unroll
    for (int nt = 0; nt < 16; nt++) {
        float d0 = acc[nt][0] - mu0, d1 = acc[nt][1] - mu0;
        float d2 = acc[nt][2] - mu1, d3 = acc[nt][3] - mu1;
        q0 = fmaf(d0, d0, q0); q0 = fmaf(d1, d1, q0);
        q1 = fmaf(d2, d2, q1); q1 = fmaf(d3, d3, q1);
    }
    q0 += __shfl_xor_sync(0xffffffffu, q0, 1);
    q0 += __shfl_xor_sync(0xffffffffu, q0, 2);
    q1 += __shfl_xor_sync(0xffffffffu, q1, 1);
    q1 += __shfl_xor_sync(0xffffffffu, q1, 2);
    float rs0 = rsqrtf(q0 * (1.f / 128.f) + 1e-5f);
    float rs1 = rsqrtf(q1 * (1.f / 128.f) + 1e-5f);
#pragma unroll
    for (int nt = 0; nt < 16; nt++) {
        int c0 = nt * 8 + qc;
        float g0 = lns[128 + c0], g1 = lns[128 + c0 + 1];
        float o0 = lns[256 + c0], o1 = lns[256 + c0 + 1];
        if (r0 < N_NODES) {
            *(unsigned*)(aggY + (size_t)r0 * H + c0) = f2h2(
                fmaxf(fmaf((acc[nt][0] - mu0) * rs0, g0, o0), 0.f),
                fmaxf(fmaf((acc[nt][1] - mu0) * rs0, g1, o1), 0.f));
        }
        if (r1 < N_NODES) {
            *(unsigned*)(aggY + (size_t)r1 * H + c0) = f2h2(
                fmaxf(fmaf((acc[nt][2] - mu1) * rs1, g0, o0), 0.f),
                fmaxf(fmaf((acc[nt][3] - mu1) * rs1, g1, o1), 0.f));
        }
    }
}

// ---------------- Pl/Pr on HMMA fp16 (verified R10-R16) ----------------
#define PP_AS 0
#define PP_WS 17408
#define PP_B1 87040
#define PP_SM 87552
__global__ void __launch_bounds__(256) k_plpr_mma(
    const __half* __restrict__ h, const __half* __restrict__ W1T,
    const float* __restrict__ b1,
    __half* __restrict__ Pl, __half* __restrict__ Pr)
{
    extern __shared__ char smc[];
    uint32_t sb = smem_u32(smc);
    int t = threadIdx.x, lane = t & 31, warp = t >> 5;
    int row0 = blockIdx.x * 64;
    int half_ = warp >> 2;
    int wm = warp & 3;
    float* b1s = (float*)(smc + PP_B1);
    if (t < 128) b1s[t] = b1[t];

#pragma unroll
    for (int p = 0; p < 4; p++) {
        int id = t + p * 256;
        int r = id >> 4, fq = id & 15;
        int row = row0 + r;
        uint4 v = make_uint4(0u, 0u, 0u, 0u);
        if (row < N_NODES)
            v = *(const uint4*)(h + (size_t)row * H + fq * 8);
        *(uint4*)(smc + PP_AS + r * 272 + fq * 16) = v;
    }
#pragma unroll
    for (int p = 0; p < 16; p++) {
        int id = t + p * 256;
        int n = id >> 4, q = id & 15;
        uint4 w = *(const uint4*)(W1T + n * 128 + q * 8);
        *(uint4*)(smc + PP_WS + n * 272 + q * 16) = w;
    }
    __syncthreads();

    float acc[16][4];
#pragma unroll
    for (int nt = 0; nt < 16; nt++)
#pragma unroll
        for (int m = 0; m < 4; m++) acc[nt][m] = 0.f;

    uint32_t a_base = sb + PP_AS + (uint32_t)(wm * 16 + (lane & 15)) * 272
                      + (uint32_t)(lane >> 4) * 16;
    uint32_t b_base = sb + PP_WS + (uint32_t)half_ * 128 * 272
                      + (uint32_t)(lane & 7) * 272 + (uint32_t)((lane >> 3) & 1) * 16;
#pragma unroll
    for (int ks = 0; ks < 8; ks++) {
        uint32_t a0, a1, a2, a3;
        ldmA(a0, a1, a2, a3, a_base + ks * 32);
#pragma unroll
        for (int nt = 0; nt < 16; nt++) {
            uint32_t b0, b1v;
            ldmB(b0, b1v, b_base + (uint32_t)nt * 8 * 272 + ks * 32);
            mma16816(acc[nt], a0, a1, a2, a3, b0, b1v);
        }
    }

    int qr = lane >> 2, qc = (lane & 3) * 2;
    int r0 = row0 + wm * 16 + qr;
    int r1 = r0 + 8;
    __half* outp = half_ ? Pr : Pl;
#pragma unroll
    for (int nt = 0; nt < 16; nt++) {
        int c0 = nt * 8 + qc;
        float add0 = half_ ? 0.f : b1s[c0];
        float add1 = half_ ? 0.f : b1s[c0 + 1];
        if (r0 < N_NODES)
            *(unsigned*)(outp + (size_t)r0 * H + c0) = f2h2(acc[nt][0] + add0, acc[nt][1] + add1);
        if (r1 < N_NODES)
            *(unsigned*)(outp + (size_t)r1 * H + c0) = f2h2(acc[nt][2] + add0, acc[nt][3] + add1);
    }
}

// ---------------- fused edge MLP; ea@W1e on HMMA, fp16 add path ----------------
// TE=256, 512 threads. Phase A: EW = EA[256][16] @ W1eT via 1 k-step HMMA, fragments
// stored fp16 into z1 smem. Phase B: z1 = relu(EW + Pl[src] + Pr[dst]) via __hadd2.
// Phase C: z2 GEMM (verified R13 pattern) + epilogue.
#define TE 256
#define ZST 136
#define EZ1_OFF   0                        // 256*272 = 69632
#define EW2T_OFF  69632                    // 64*272  = 17408 -> 87040
#define EEA_OFF   87040                    // 256*32  = 8192  -> 95232
#define EW1E_OFF  95232                    // 128*32  = 4096  -> 99328
#define EW3_OFF   99328                    // 64 f32 -> 99584
#define EB2_OFF   99584                    // 64 f32 -> 99840
#define ESM_TOTAL 99840

__global__ void __launch_bounds__(512) k_edge(
    const int* __restrict__ src, const int* __restrict__ dst,
    const float* __restrict__ ea, const __half* __restrict__ Pl,
    const __half* __restrict__ Pr,
    const __half* __restrict__ W2T, const __half* __restrict__ W1eT,
    const float* __restrict__ b2,
    const float* __restrict__ W3, const float* __restrict__ b3,
    float* __restrict__ out)
{
    extern __shared__ char smc[];
    uint32_t sb = smem_u32(smc);

    float* W3s = (float*)(smc + EW3_OFF);
    float* b2s = (float*)(smc + EB2_OFF);

    int t = threadIdx.x;
    int lane = t & 31, warp = t >> 5;
    int e0 = blockIdx.x * TE;

    // ---- stage: W2T, W3, b2, W1eT, EA
    if (t < 64) { W3s[t] = W3[t]; b2s[t] = b2[t]; }
#pragma unroll
    for (int p = 0; p < 2; p++) {
        int id = t + p * 512;
        int n = id >> 4, q = id & 15;
        uint4 w = *(const uint4*)(W2T + n * 128 + q * 8);
        *(uint4*)(smc + EW2T_OFF + n * 272 + q * 16) = w;
    }
    if (t < 256) {
        // W1eT: 128 rows x 32 B = 256 uint4
        int n = t >> 1, q = t & 1;
        uint4 w = *(const uint4*)(W1eT + n * 16 + q * 8);
        *(uint4*)(smc + EW1E_OFF + n * 32 + q * 16) = w;
    }
    if (t < 256) {
        // EA: edge t, 12 floats (48 B, float4-aligned) -> fp16 [t][16], pad 0
        const float4* ep = (const float4*)(ea + (size_t)(e0 + t) * 12);
        float4 f0 = ep[0], f1 = ep[1], f2 = ep[2];
        uint4 o;
        o.x = f2h2(f0.x, f0.y); o.y = f2h2(f0.z, f0.w);
        o.z = f2h2(f1.x, f1.y); o.w = f2h2(f1.z, f1.w);
        *(uint4*)(smc + EEA_OFF + t * 32) = o;
        uint4 o2;
        o2.x = f2h2(f2.x, f2.y); o2.y = f2h2(f2.z, f2.w);
        o2.z = 0u; o2.w = 0u;
        *(uint4*)(smc + EEA_OFF + t * 32 + 16) = o2;
    }
    __syncthreads();   // staging complete before MMA reads (R12 lesson)

    // ---- phase A: EW = EA @ W1eT  (M=256, N=128, K=16); warp owns 16 edges
    {
        int m0 = warp * 16;
        uint32_t a_base = sb + EEA_OFF + (uint32_t)(m0 + (lane & 15)) * 32
                          + (uint32_t)(lane >> 4) * 16;
        uint32_t b_base = sb + EW1E_OFF + (uint32_t)(lane & 7) * 32
                          + (uint32_t)((lane >> 3) & 1) * 16;
        uint32_t a0, a1, a2, a3;
        ldmA(a0, a1, a2, a3, a_base);
        int qr = lane >> 2, qc = (lane & 3) * 2;
#pragma unroll
        for (int nt = 0; nt < 16; nt++) {
            float acw[4] = {0.f, 0.f, 0.f, 0.f};
            uint32_t b0, b1v;
            ldmB(b0, b1v, b_base + (uint32_t)nt * 256);
            mma16816(acw, a0, a1, a2, a3, b0, b1v);
            int col = nt * 8 + qc;
            *(unsigned*)(smc + EZ1_OFF + (m0 + qr) * 272 + col * 2) = f2h2(acw[0], acw[1]);
            *(unsigned*)(smc + EZ1_OFF + (m0 + qr + 8) * 272 + col * 2) = f2h2(acw[2], acw[3]);
        }
    }
    __syncthreads();   // EW in z1 smem before phase B reads

    // ---- phase B: z1 = relu(EW + Pl[src] + Pr[dst]); 2 threads/edge
    {
        int el = t >> 1;
        int jh = t & 1;
        int eg = e0 + el;
        int s = src[eg], d = dst[eg];
        const uint4* pl4 = (const uint4*)(Pl + (size_t)s * H);
        const uint4* pr4 = (const uint4*)(Pr + (size_t)d * H);
#pragma unroll
        for (int g = 0; g < 8; g++) {
            int grp = jh * 8 + g;
            int jb = grp * 8;
            uint4 ew = *(uint4*)(smc + EZ1_OFF + el * 272 + jb * 2);
            uint4 a = pl4[grp];
            uint4 b = pr4[grp];
            uint4 z;
            z.x = hadd3_relu(ew.x, a.x, b.x);
            z.y = hadd3_relu(ew.y, a.y, b.y);
            z.z = hadd3_relu(ew.z, a.z, b.z);
            z.w = hadd3_relu(ew.w, a.w, b.w);
            *(uint4*)(smc + EZ1_OFF + el * 272 + jb * 2) = z;
        }
    }
    __syncthreads();

    // ---- phase C: z2 GEMM, 16 warps x (M=16, N=64), K=128 (verified R13)
    int m0 = warp * 16;
    float acc[8][4];
#pragma unroll
    for (int nt = 0; nt < 8; nt++)
#pragma unroll
        for (int m = 0; m < 4; m++) acc[nt][m] = 0.f;

    uint32_t a_base = sb + EZ1_OFF + (uint32_t)(m0 + (lane & 15)) * (ZST * 2)
                      + (uint32_t)(lane >> 4) * 16;
    uint32_t b_base = sb + EW2T_OFF + (uint32_t)(lane & 7) * (ZST * 2)
                      + (uint32_t)((lane >> 3) & 1) * 16;

#pragma unroll
    for (int ks = 0; ks < 8; ks++) {
        uint32_t a0, a1, a2, a3;
        ldmA(a0, a1, a2, a3, a_base + ks * 32);
#pragma unroll
        for (int nt = 0; nt < 8; nt++) {
            uint32_t b0, b1v;
            ldmB(b0, b1v, b_base + (uint32_t)nt * 8 * (ZST * 2) + ks * 32);
            mma16816(acc[nt], a0, a1, a2, a3, b0, b1v);
        }
    }

    int qr = lane >> 2;
    int qc = (lane & 3) * 2;
    float p0 = 0.f, p1 = 0.f;
#pragma unroll
    for (int nt = 0; nt < 8; nt++) {
        int c0 = nt * 8 + qc, c1 = c0 + 1;
        float w30 = W3s[c0], w31 = W3s[c1];
        float bb0 = b2s[c0], bb1 = b2s[c1];
        p0 = fmaf(fmaxf(acc[nt][0] + bb0, 0.f), w30, p0);
        p0 = fmaf(fmaxf(acc[nt][1] + bb1, 0.f), w31, p0);
        p1 = fmaf(fmaxf(acc[nt][2] + bb0, 0.f), w30, p1);
        p1 = fmaf(fmaxf(acc[nt][3] + bb1, 0.f), w31, p1);
    }
    p0 += __shfl_xor_sync(0xffffffffu, p0, 1);
    p0 += __shfl_xor_sync(0xffffffffu, p0, 2);
    p1 += __shfl_xor_sync(0xffffffffu, p1, 1);
    p1 += __shfl_xor_sync(0xffffffffu, p1, 2);
    if ((lane & 3) == 0) {
        float b3v = b3[0];
        float x0 = p0 + b3v;
        float x1 = p1 + b3v;
        out[e0 + m0 + qr]     = fmaxf(x0, 0.f) + log1pf(expf(-fabsf(x0)));
        out[e0 + m0 + qr + 8] = fmaxf(x1, 0.f) + log1pf(expf(-fabsf(x1)));
    }
}

// ---------------- launch (single stream, verified R13/R16 ordering) ----------------
extern "C" void kernel_launch(void* const* d_in, const int* in_sizes, int n_in,
                              void* d_out, int out_size) {
    const float* x      = (const float*)d_in[0];
    const int*   ei     = (const int*)d_in[1];
    const float* ea     = (const float*)d_in[2];
    const float* node_W = (const float*)d_in[3];
    const float* node_b = (const float*)d_in[4];
    const float* sWl    = (const float*)d_in[5];
    const float* sbl    = (const float*)d_in[6];
    const float* sWr    = (const float*)d_in[7];
    const float* ln_g   = (const float*)d_in[8];
    const float* ln_b   = (const float*)d_in[9];
    const float* W1     = (const float*)d_in[10];
    const float* b1     = (const float*)d_in[11];
    const float* W2     = (const float*)d_in[12];
    const float* b2     = (const float*)d_in[13];
    const float* W3     = (const float*)d_in[14];
    const float* b3     = (const float*)d_in[15];
    float* out = (float*)d_out;
    const int* src = ei;
    const int* dstp = ei + N_EDGES;

    __half *pA, *pB, *pPl, *pPr, *pWsT, *pW1T, *pW2T, *pW1eT;
    int *pDegi, *pLoc, *pBsum, *pBoff, *pOff, *pCur, *pCsr;
    cudaGetSymbolAddress((void**)&pA, g_bufA);
    cudaGetSymbolAddress((void**)&pB, g_bufB);
    cudaGetSymbolAddress((void**)&pPl, g_Plh);
    cudaGetSymbolAddress((void**)&pPr, g_Prh);
    cudaGetSymbolAddress((void**)&pWsT, g_WsT);
    cudaGetSymbolAddress((void**)&pW1T, g_W1T);
    cudaGetSymbolAddress((void**)&pW2T, g_W2T);
    cudaGetSymbolAddress((void**)&pW1eT, g_W1eT);
    cudaGetSymbolAddress((void**)&pDegi, g_degi);
    cudaGetSymbolAddress((void**)&pLoc, g_loc);
    cudaGetSymbolAddress((void**)&pBsum, g_bsum);
    cudaGetSymbolAddress((void**)&pBoff, g_boff);
    cudaGetSymbolAddress((void**)&pOff, g_off);
    cudaGetSymbolAddress((void**)&pCur, g_cur);
    cudaGetSymbolAddress((void**)&pCsr, g_csr);

    // CSR build
    cudaMemsetAsync(pDegi, 0, N_NODES * sizeof(int));
    k_deg<<<(N_EDGES + 255) / 256, 256>>>(dstp, pDegi);
    k_scan1<<<NB, 256>>>(pDegi, pLoc, pBsum);
    k_scan2<<<1, 512>>>(pBsum, pBoff);
    k_scan3<<<(N_NODES + 255) / 256, 256>>>(pLoc, pBoff, pOff, pCur);
    k_csrfill<<<(N_EDGES + 255) / 256, 256>>>(src, dstp, pCur, pCsr);

    k_wprep<<<(3 * 128 * 256 + 255) / 256, 256>>>(sWl, sWr, W1, W2, pWsT, pW1T, pW2T, pW1eT);
    k_nodeproj<<<(N_NODES * 16 + 255) / 256, 256>>>(x, node_W, node_b, pA);

    cudaFuncSetAttribute(k_sage_mma, cudaFuncAttributeMaxDynamicSharedMemorySize, SG_SM);
    cudaFuncSetAttribute(k_plpr_mma, cudaFuncAttributeMaxDynamicSharedMemorySize, PP_SM);
    cudaFuncSetAttribute(k_edge, cudaFuncAttributeMaxDynamicSharedMemorySize, ESM_TOTAL);

    __half* hcur = pA;
    __half* other = pB;
    for (int l = 0; l < 3; l++) {
        k_gather<<<(N_NODES * 32 + 255) / 256, 256>>>(pOff, pCsr, hcur, other);
        k_sage_mma<<<(N_NODES + 127) / 128, 256, SG_SM>>>(
            hcur, other, pWsT + (size_t)l * 128 * 256, sbl + l * H,
            ln_g + l * H, ln_b + l * H);
        __half* tmp = hcur; hcur = other; other = tmp;
    }

    k_plpr_mma<<<(N_NODES + 63) / 64, 256, PP_SM>>>(hcur, pW1T, b1, pPl, pPr);

    k_edge<<<N_EDGES / TE, 512, ESM_TOTAL>>>(src, dstp, ea, pPl, pPr,
                                             pW2T, pW1eT, b2, W3, b3, out);
}